// round 9
// baseline (speedup 1.0000x reference)
#include <cuda_runtime.h>
#include <cstdint>
#include <cstddef>
typedef unsigned long long ull;
#define C3 384

__device__ float g_xw[(size_t)1024 * 256 * C3];     // [t][b][384] gate pre-acts
__device__ float g_seq1[(size_t)1024 * 256 * 128];  // [t][b][128] layer-1 outputs

__device__ __forceinline__ ull ffma2(ull a, ull b, ull c) {
    ull d; asm("fma.rn.f32x2 %0,%1,%2,%3;" : "=l"(d) : "l"(a), "l"(b), "l"(c)); return d;
}
__device__ __forceinline__ ull pack2(float x, float y) {
    ull d; asm("mov.b64 %0,{%1,%2};" : "=l"(d) : "f"(x), "f"(y)); return d;
}
__device__ __forceinline__ float2 up2(ull v) {
    float x, y; asm("mov.b64 {%0,%1},%2;" : "=f"(x), "=f"(y) : "l"(v)); return make_float2(x, y);
}
__device__ __forceinline__ float sigm(float x) {
    return __fdividef(1.f, 1.f + __expf(-x));
}
__device__ __forceinline__ void pfL2(const void* p) {
    asm volatile("prefetch.global.L2 [%0];" :: "l"(p));
}

// ============================================================
// k_xw v4: out[t*256+b][c] = sum_k in[row][k]*W[k][c] + bias[c]
// 32-row chunks; thread = (col-quad cq: 4 cols, rowgroup rg: 8 rows).
// acc = 32 ull = 64 regs -> no spill. W staged once in smem [K/2][192].
// ============================================================
template<int K, bool L1>
__global__ void __launch_bounds__(384, 1) k_xw(const float* __restrict__ in,
                                               const float* __restrict__ W,
                                               const float* __restrict__ bias) {
    extern __shared__ __align__(16) char smraw[];
    ulonglong2* Wp = (ulonglong2*)smraw;                       // [K/2][192]
    float* xs = (float*)(smraw + (size_t)(K / 2) * 192 * 16);  // [32][K]
    int tid = threadIdx.x;
    int cq = tid % 96, rg = tid / 96;
    int rbase = rg * 8;

    // Wp[j*192+cp] = {(W[2j][2cp],W[2j+1][2cp]), (W[2j][2cp+1],W[2j+1][2cp+1])}
    for (int i = tid; i < (K / 2) * 192; i += 384) {
        int j = i / 192, c2 = i % 192;
        const float* w0 = W + (size_t)(2 * j) * C3 + 2 * c2;
        Wp[i] = make_ulonglong2(pack2(w0[0], w0[C3]), pack2(w0[1], w0[C3 + 1]));
    }
    float4 bq = *(const float4*)&bias[4 * cq];
    __syncthreads();

    for (int ch = blockIdx.x; ch < 8192; ch += gridDim.x) {
        int r0 = ch * 32;
        const float4* src = (const float4*)((L1 ? in : (const float*)g_seq1) + (size_t)r0 * K);
        __syncthreads();
        for (int i = tid; i < 32 * K / 4; i += 384) ((float4*)xs)[i] = src[i];
        __syncthreads();

        ull acc0[8], acc1[8], acc2[8], acc3[8];
#pragma unroll
        for (int r = 0; r < 8; r++) { acc0[r] = 0; acc1[r] = 0; acc2[r] = 0; acc3[r] = 0; }

        for (int kq = 0; kq < K / 4; kq++) {
            ulonglong2 wA0 = Wp[(2 * kq) * 192 + 2 * cq];
            ulonglong2 wA1 = Wp[(2 * kq) * 192 + 2 * cq + 1];
            ulonglong2 wB0 = Wp[(2 * kq + 1) * 192 + 2 * cq];
            ulonglong2 wB1 = Wp[(2 * kq + 1) * 192 + 2 * cq + 1];
            const float* xrow = xs + (size_t)rbase * K + 4 * kq;
#pragma unroll
            for (int r = 0; r < 8; r++) {
                ulonglong2 x4 = *(const ulonglong2*)(xrow + (size_t)r * K);  // broadcast
                acc0[r] = ffma2(x4.x, wA0.x, acc0[r]);
                acc1[r] = ffma2(x4.x, wA0.y, acc1[r]);
                acc2[r] = ffma2(x4.x, wA1.x, acc2[r]);
                acc3[r] = ffma2(x4.x, wA1.y, acc3[r]);
                acc0[r] = ffma2(x4.y, wB0.x, acc0[r]);
                acc1[r] = ffma2(x4.y, wB0.y, acc1[r]);
                acc2[r] = ffma2(x4.y, wB1.x, acc2[r]);
                acc3[r] = ffma2(x4.y, wB1.y, acc3[r]);
            }
        }

#pragma unroll
        for (int r = 0; r < 8; r++) {
            float2 v0 = up2(acc0[r]), v1 = up2(acc1[r]);
            float2 v2 = up2(acc2[r]), v3 = up2(acc3[r]);
            int rr = r0 + rbase + r;
            int orow = L1 ? ((rr & 1023) * 256 + (rr >> 10)) : rr;
            float4 o = make_float4(v0.x + v0.y + bq.x, v1.x + v1.y + bq.y,
                                   v2.x + v2.y + bq.z, v3.x + v3.y + bq.w);
            *(float4*)&g_xw[(size_t)orow * C3 + 4 * cq] = o;
        }
    }
}

// ============================================================
// k_gru v4: split-K, 768 threads (24 warps). thread = (col, k-half).
// Each thread: 32 packed weight k-pairs (64 regs), half the dot.
// Partials combined in smem by gate threads. Still 2 barriers/step.
// ============================================================
template<bool WSEQ>
__global__ void __launch_bounds__(768, 1) k_gru(const float* __restrict__ Uw,
                                                const float* __restrict__ br,
                                                float* __restrict__ stateOut,
                                                float* __restrict__ xOut) {
    __shared__ __align__(16) float hsi[256];   // interleaved 2-batch h, ordered by k
    __shared__ __align__(8) float2 part[768];  // per-thread partial (b0, b1)
    int c = threadIdx.x, p = blockIdx.x;
    int half = (c >= 384) ? 1 : 0;
    int col = c - 384 * half;

    ull wp[32];
    int kk0 = half * 64;
#pragma unroll
    for (int j = 0; j < 32; j++)
        wp[j] = pack2(Uw[(size_t)(kk0 + 2 * j) * C3 + col],
                      Uw[(size_t)(kk0 + 2 * j + 1) * C3 + col]);
    float bias0 = half ? 0.f : br[col];
    int hbase = 128 * half;

    if (c < 256) hsi[c] = 0.f;
    int u = c & 127, bl = (c >> 7) & 1;
    bool g = c < 256;
    int b = 2 * p + bl;
    int hidx = 4 * (u >> 1) + 2 * bl + (u & 1);
    const float* xq = g_xw + (size_t)b * C3 + u;
    float* sq = g_seq1 + (size_t)b * 128 + u;
    bool pf = g && ((u & 31) == 0);
    float hval = 0.f;
    __syncthreads();

    for (int t = 0; t < 1024; t++) {
        float xz = 0.f, xr = 0.f, xh = 0.f;
        if (g) {
            const float* q = xq + (size_t)t * (256 * C3);
            xz = q[0]; xr = q[128]; xh = q[256];
        }
        if (pf && t < 1023) {
            const float* q = xq + (size_t)(t + 1) * (256 * C3);
            pfL2(q); pfL2(q + 128); pfL2(q + 256);
        }
        ull a0 = 0ull, a1 = 0ull;
#pragma unroll
        for (int j = 0; j < 32; j++) {
            ulonglong2 q = *(const ulonglong2*)&hsi[hbase + 4 * j];
            a0 = ffma2(q.x, wp[j], a0);
            a1 = ffma2(q.y, wp[j], a1);
        }
        float2 v0 = up2(a0), v1 = up2(a1);
        part[c] = make_float2(v0.x + v0.y + bias0, v1.x + v1.y + bias0);
        __syncthreads();
        if (g) {
            float2 pza = part[u],       pzb = part[u + 384];
            float2 pra = part[u + 128], prb = part[u + 512];
            float2 pha = part[u + 256], phb = part[u + 640];
            float rz = bl ? (pza.y + pzb.y) : (pza.x + pzb.x);
            float rr = bl ? (pra.y + prb.y) : (pra.x + prb.x);
            float rh = bl ? (pha.y + phb.y) : (pha.x + phb.x);
            float z  = sigm(xz + rz);
            float r  = sigm(xr + rr);
            float hh = fmaxf(xh + r * rh, 0.f);
            float hn = z * hval + (1.f - z) * hh;
            hval = hn;
            hsi[hidx] = hn;
            if (WSEQ) sq[(size_t)t * (256 * 128)] = hn;
            if (t == 1023) {
                stateOut[(size_t)b * 128 + u] = hn;
                if (xOut) xOut[(size_t)b * 128 + u] = hn;
            }
        }
        __syncthreads();
    }
}

extern "C" void kernel_launch(void* const* d_in, const int* in_sizes, int n_in,
                              void* d_out, int out_size) {
    const float* x  = (const float*)d_in[0];
    const float* W1 = (const float*)d_in[1];
    const float* U1 = (const float*)d_in[2];
    const float* b1 = (const float*)d_in[3];
    const float* W2 = (const float*)d_in[4];
    const float* U2 = (const float*)d_in[5];
    const float* b2 = (const float*)d_in[6];
    float* out = (float*)d_out;  // [x | state1 | state2], each 256*128

    int sm1 = (64 / 2) * 192 * 16 + 32 * 64 * 4;     // 98304 + 8192  = 106496
    int sm2 = (128 / 2) * 192 * 16 + 32 * 128 * 4;   // 196608 + 16384 = 212992
    cudaFuncSetAttribute(k_xw<64, true>,   cudaFuncAttributeMaxDynamicSharedMemorySize, sm1);
    cudaFuncSetAttribute(k_xw<128, false>, cudaFuncAttributeMaxDynamicSharedMemorySize, sm2);

    k_xw<64, true><<<148, 384, sm1>>>(x, W1, b1);
    k_gru<true><<<128, 768>>>(U1, b1 + C3, out + 32768, nullptr);
    k_xw<128, false><<<148, 384, sm2>>>(nullptr, W2, b2);
    k_gru<false><<<128, 768>>>(U2, b2 + C3, out + 65536, out);
}

// round 10
// speedup vs baseline: 1.2518x; 1.2518x over previous
#include <cuda_runtime.h>
#include <cstdint>
#include <cstddef>
typedef unsigned long long ull;
#define C3 384

__device__ float g_xw[(size_t)1024 * 256 * C3];     // [t][b][384] gate pre-acts
__device__ float g_seq1[(size_t)1024 * 256 * 128];  // [t][b][128] layer-1 outputs

__device__ __forceinline__ ull ffma2(ull a, ull b, ull c) {
    ull d; asm("fma.rn.f32x2 %0,%1,%2,%3;" : "=l"(d) : "l"(a), "l"(b), "l"(c)); return d;
}
__device__ __forceinline__ ull pack2(float x, float y) {
    ull d; asm("mov.b64 %0,{%1,%2};" : "=l"(d) : "f"(x), "f"(y)); return d;
}
__device__ __forceinline__ float2 up2(ull v) {
    float x, y; asm("mov.b64 {%0,%1},%2;" : "=f"(x), "=f"(y) : "l"(v)); return make_float2(x, y);
}
__device__ __forceinline__ float sigm(float x) {
    return __fdividef(1.f, 1.f + __expf(-x));
}
__device__ __forceinline__ void pfL2(const void* p) {
    asm volatile("prefetch.global.L2 [%0];" :: "l"(p));
}
__device__ __forceinline__ void cpa16(void* s, const void* g) {
    uint32_t sa = (uint32_t)__cvta_generic_to_shared(s);
    asm volatile("cp.async.ca.shared.global [%0], [%1], 16;" :: "r"(sa), "l"(g));
}
__device__ __forceinline__ void cpa_commit() { asm volatile("cp.async.commit_group;"); }
__device__ __forceinline__ void cpa_wait0() { asm volatile("cp.async.wait_group 0;"); }

// ============================================================
// k_xw v5: out[t*256+b][c] = sum_k in[row][k]*W[k][c] + bias[c]
// 32-row chunks, cp.async double-buffered; thread = (col-pair, 16 rows).
// acc = 32 ull = 64 regs. W staged once in smem [K/2][192].
// ============================================================
template<int K, bool L1>
__global__ void __launch_bounds__(384, 1) k_xw(const float* __restrict__ in,
                                               const float* __restrict__ W,
                                               const float* __restrict__ bias) {
    extern __shared__ __align__(16) char smraw[];
    ulonglong2* Wp = (ulonglong2*)smraw;                       // [K/2][192]
    float* xs0 = (float*)(smraw + (size_t)(K / 2) * 192 * 16); // buf0 [32][K]
    float* xs1 = xs0 + 32 * K;                                 // buf1 [32][K]
    int tid = threadIdx.x;
    int cp = tid % 192, rg = tid / 192;
    int rbase = rg * 16;
    const float* base = L1 ? in : (const float*)g_seq1;

    for (int i = tid; i < (K / 2) * 192; i += 384) {
        int j = i / 192, c2 = i % 192;
        const float* w0 = W + (size_t)(2 * j) * C3 + 2 * c2;
        Wp[i] = make_ulonglong2(pack2(w0[0], w0[C3]), pack2(w0[1], w0[C3 + 1]));
    }
    float2 bq = *(const float2*)&bias[2 * cp];
    __syncthreads();

    constexpr int NV = 32 * K / 4;   // float4s per chunk
    int ch = blockIdx.x;
    if (ch < 8192) {  // prologue: stage first chunk into buf0
        const float4* src = (const float4*)(base + (size_t)ch * 32 * K);
        for (int i = tid; i < NV; i += 384) cpa16(&xs0[i * 4], &src[i]);
    }
    cpa_commit();
    int buf = 0;

    for (; ch < 8192; ch += gridDim.x) {
        float* cur = buf ? xs1 : xs0;
        float* nxtb = buf ? xs0 : xs1;
        cpa_wait0();
        __syncthreads();          // cur ready for all; prev compute done -> nxtb writable
        int nch = ch + gridDim.x;
        if (nch < 8192) {
            const float4* src = (const float4*)(base + (size_t)nch * 32 * K);
            for (int i = tid; i < NV; i += 384) cpa16(&nxtb[i * 4], &src[i]);
        }
        cpa_commit();

        ull acc0[16], acc1[16];
#pragma unroll
        for (int r = 0; r < 16; r++) { acc0[r] = 0; acc1[r] = 0; }
        for (int kq = 0; kq < K / 4; kq++) {
            ulonglong2 wA = Wp[(2 * kq) * 192 + cp];       // k(4kq,4kq+1), cols 2cp,2cp+1
            ulonglong2 wB = Wp[(2 * kq + 1) * 192 + cp];   // k(4kq+2,4kq+3)
            const float* xrow = cur + (size_t)rbase * K + 4 * kq;
#pragma unroll
            for (int r = 0; r < 16; r++) {
                ulonglong2 x4 = *(const ulonglong2*)(xrow + (size_t)r * K);  // broadcast
                acc0[r] = ffma2(x4.x, wA.x, acc0[r]);
                acc1[r] = ffma2(x4.x, wA.y, acc1[r]);
                acc0[r] = ffma2(x4.y, wB.x, acc0[r]);
                acc1[r] = ffma2(x4.y, wB.y, acc1[r]);
            }
        }
#pragma unroll
        for (int r = 0; r < 16; r++) {
            float2 v0 = up2(acc0[r]), v1 = up2(acc1[r]);
            int rr = ch * 32 + rbase + r;
            int orow = L1 ? ((rr & 1023) * 256 + (rr >> 10)) : rr;
            float2 o = make_float2(v0.x + v0.y + bq.x, v1.x + v1.y + bq.y);
            *(float2*)&g_xw[(size_t)orow * C3 + 2 * cp] = o;
        }
        buf ^= 1;
    }
}

// ============================================================
// k_gru (reverted to R6 v3 best): 1 CTA = 2 batch rows; 384 threads = cols.
// Interleaved h; recurrent weights register-resident (64 packed k-pairs).
// ============================================================
template<bool WSEQ>
__global__ void __launch_bounds__(384, 1) k_gru(const float* __restrict__ Uw,
                                                const float* __restrict__ br,
                                                float* __restrict__ stateOut,
                                                float* __restrict__ xOut) {
    __shared__ __align__(16) float hsi[256];
    __shared__ __align__(8) float2 rss[C3];
    int c = threadIdx.x, p = blockIdx.x;
    ull wp[64];
#pragma unroll
    for (int j = 0; j < 64; j++)
        wp[j] = pack2(Uw[(size_t)(2 * j) * C3 + c], Uw[(size_t)(2 * j + 1) * C3 + c]);
    float brc = br[c];
    if (c < 256) hsi[c] = 0.f;
    int u = c & 127, bl = (c >> 7) & 1;
    bool g = c < 256;
    int b = 2 * p + bl;
    int hidx = 4 * (u >> 1) + 2 * bl + (u & 1);
    const float* xq = g_xw + (size_t)b * C3 + u;
    float* sq = g_seq1 + (size_t)b * 128 + u;
    bool pf = g && ((u & 31) == 0);
    float hval = 0.f;
    __syncthreads();
    for (int t = 0; t < 1024; t++) {
        float xz = 0.f, xr = 0.f, xh = 0.f;
        if (g) {
            const float* q = xq + (size_t)t * (256 * C3);
            xz = q[0]; xr = q[128]; xh = q[256];
        }
        if (pf && t < 1023) {
            const float* q = xq + (size_t)(t + 1) * (256 * C3);
            pfL2(q); pfL2(q + 128); pfL2(q + 256);
        }
        ull a0 = 0ull, a1 = 0ull;
#pragma unroll
        for (int j = 0; j < 64; j++) {
            ulonglong2 q = *(const ulonglong2*)&hsi[4 * j];
            a0 = ffma2(q.x, wp[j], a0);
            a1 = ffma2(q.y, wp[j], a1);
        }
        float2 v0 = up2(a0), v1 = up2(a1);
        rss[c] = make_float2(v0.x + v0.y + brc, v1.x + v1.y + brc);
        __syncthreads();
        if (g) {
            float2 rz = rss[u], rr2 = rss[u + 128], rh = rss[u + 256];
            float z  = sigm(xz + (bl ? rz.y : rz.x));
            float r  = sigm(xr + (bl ? rr2.y : rr2.x));
            float hh = fmaxf(xh + r * (bl ? rh.y : rh.x), 0.f);
            float hn = z * hval + (1.f - z) * hh;
            hval = hn;
            hsi[hidx] = hn;
            if (WSEQ) sq[(size_t)t * (256 * 128)] = hn;
            if (t == 1023) {
                stateOut[(size_t)b * 128 + u] = hn;
                if (xOut) xOut[(size_t)b * 128 + u] = hn;
            }
        }
        __syncthreads();
    }
}

extern "C" void kernel_launch(void* const* d_in, const int* in_sizes, int n_in,
                              void* d_out, int out_size) {
    const float* x  = (const float*)d_in[0];
    const float* W1 = (const float*)d_in[1];
    const float* U1 = (const float*)d_in[2];
    const float* b1 = (const float*)d_in[3];
    const float* W2 = (const float*)d_in[4];
    const float* U2 = (const float*)d_in[5];
    const float* b2 = (const float*)d_in[6];
    float* out = (float*)d_out;  // [x | state1 | state2], each 256*128

    int sm1 = (64 / 2) * 192 * 16 + 2 * 32 * 64 * 4;     // 98304 + 16384  = 114688
    int sm2 = (128 / 2) * 192 * 16 + 2 * 32 * 128 * 4;   // 196608 + 32768 = 229376
    cudaFuncSetAttribute(k_xw<64, true>,   cudaFuncAttributeMaxDynamicSharedMemorySize, sm1);
    cudaFuncSetAttribute(k_xw<128, false>, cudaFuncAttributeMaxDynamicSharedMemorySize, sm2);

    k_xw<64, true><<<148, 384, sm1>>>(x, W1, b1);
    k_gru<true><<<128, 384>>>(U1, b1 + C3, out + 32768, nullptr);
    k_xw<128, false><<<148, 384, sm2>>>(nullptr, W2, b2);
    k_gru<false><<<128, 384>>>(U2, b2 + C3, out + 65536, out);
}